// round 8
// baseline (speedup 1.0000x reference)
#include <cuda_runtime.h>

// SpatialTransformer: trilinear warp of vol[0] ([160,192,224,2] f32) by dense
// shift field trf[0] ([160,192,224,3] f32). Reference semantics: loc clipped,
// loc0=clip(floor), loc1=clip(loc0+1), w_c0=loc1-loc.
//
// R7 model: L1tex wavefront-bound on scattered corner gathers. Fix: 3-D smem
// tile. Block = 8x8x56 output voxels; stage 15x15x63 float2 halo (+/-3) with
// coalesced loads; serve the 8 corner fetches from shared memory (bank phases
// instead of line wavefronts). Voxels whose shift exceeds the +/-3 halo
// (P ~ 0.8%) take a predicated gmem fallback with identical math.

static constexpr int D0 = 160;
static constexpr int D1 = 192;
static constexpr int D2 = 224;

static constexpr int TX = 8,  TY = 8,  TZ = 56;    // output tile per block
static constexpr int HX = 15, HY = 15, HZ = 63;    // halo'd input tile dims
static constexpr int ZP = 65;                      // padded z pitch (float2)
static constexpr int NTHREADS = 512;
static constexpr int VPT = (TX * TY * TZ) / NTHREADS;  // 7 voxels/thread
static constexpr int SMEM_BYTES = HX * HY * ZP * (int)sizeof(float2);  // 117000

__global__ __launch_bounds__(NTHREADS, 1) void st_warp_kernel(
    const float* __restrict__ vol,   // [D0,D1,D2,2]
    const float* __restrict__ trf,   // [D0,D1,D2,3]
    float2* __restrict__ out)        // [D0,D1,D2] of float2
{
    extern __shared__ float2 sv[];   // [HX][HY][ZP]

    const float2* v2 = (const float2*)vol;

    int X0 = blockIdx.x * TX;
    int Y0 = blockIdx.y * TY;
    int Z0 = blockIdx.z * TZ;
    int tid = threadIdx.x;

    // ---- stage halo'd tile (clamped source coords), coalesced along z ----
    for (int idx = tid; idx < HX * HY * HZ; idx += NTHREADS) {
        int pz = idx % HZ;
        int r  = idx / HZ;
        int py = r % HY;
        int px = r / HY;
        int gx = min(max(X0 - 3 + px, 0), D0 - 1);
        int gy = min(max(Y0 - 3 + py, 0), D1 - 1);
        int gz = min(max(Z0 - 3 + pz, 0), D2 - 1);
        sv[(px * HY + py) * ZP + pz] = v2[(gx * D1 + gy) * D2 + gz];
    }
    __syncthreads();

    const float mx = (float)(D0 - 1);
    const float my = (float)(D1 - 1);
    const float mz = (float)(D2 - 1);

    #pragma unroll
    for (int k = 0; k < VPT; k++) {
        int v  = k * NTHREADS + tid;      // 0 .. TX*TY*TZ-1
        int z  = v % TZ;
        int r  = v / TZ;
        int yl = r % TY;
        int xl = r / TY;
        int x  = X0 + xl;
        int y  = Y0 + yl;
        int zg = Z0 + z;
        int i  = (x * D1 + y) * D2 + zg;  // flat voxel index

        float sx = __ldg(&trf[3 * i + 0]);
        float sy = __ldg(&trf[3 * i + 1]);
        float sz = __ldg(&trf[3 * i + 2]);

        float lx = fminf(fmaxf((float)x  + sx, 0.0f), mx);
        float ly = fminf(fmaxf((float)y  + sy, 0.0f), my);
        float lz = fminf(fmaxf((float)zg + sz, 0.0f), mz);

        float fx0 = floorf(lx), fy0 = floorf(ly), fz0 = floorf(lz);
        float fx1 = fminf(fx0 + 1.0f, mx);
        float fy1 = fminf(fy0 + 1.0f, my);
        float fz1 = fminf(fz0 + 1.0f, mz);

        // reference weights: w_c0 = loc1 - loc, w_c1 = 1 - w_c0
        float wx0 = fx1 - lx, wx1 = 1.0f - wx0;
        float wy0 = fy1 - ly, wy1 = 1.0f - wy0;
        float wz0 = fz1 - lz, wz1 = 1.0f - wz0;

        int x0 = (int)fx0, x1 = (int)fx1;
        int y0 = (int)fy0, y1 = (int)fy1;
        int z0 = (int)fz0, z1 = (int)fz1;

        // tile-local corner coords
        int tix0 = x0 - X0 + 3, tix1 = x1 - X0 + 3;
        int tiy0 = y0 - Y0 + 3, tiy1 = y1 - Y0 + 3;
        int tiz0 = z0 - Z0 + 3, tiz1 = z1 - Z0 + 3;

        bool inTile = (tix0 >= 0) & (tix1 < HX) &
                      (tiy0 >= 0) & (tiy1 < HY) &
                      (tiz0 >= 0) & (tiz1 < HZ);

        float2 c000, c001, c010, c011, c100, c101, c110, c111;
        if (inTile) {
            int a0 = tix0 * HY, a1 = tix1 * HY;
            int s00 = (a0 + tiy0) * ZP;
            int s01 = (a0 + tiy1) * ZP;
            int s10 = (a1 + tiy0) * ZP;
            int s11 = (a1 + tiy1) * ZP;
            c000 = sv[s00 + tiz0];  c001 = sv[s00 + tiz1];
            c010 = sv[s01 + tiz0];  c011 = sv[s01 + tiz1];
            c100 = sv[s10 + tiz0];  c101 = sv[s10 + tiz1];
            c110 = sv[s11 + tiz0];  c111 = sv[s11 + tiz1];
        } else {
            int bx0 = x0 * D1, bx1 = x1 * D1;
            int r00 = (bx0 + y0) * D2;
            int r01 = (bx0 + y1) * D2;
            int r10 = (bx1 + y0) * D2;
            int r11 = (bx1 + y1) * D2;
            c000 = __ldg(&v2[r00 + z0]);  c001 = __ldg(&v2[r00 + z1]);
            c010 = __ldg(&v2[r01 + z0]);  c011 = __ldg(&v2[r01 + z1]);
            c100 = __ldg(&v2[r10 + z0]);  c101 = __ldg(&v2[r10 + z1]);
            c110 = __ldg(&v2[r11 + z0]);  c111 = __ldg(&v2[r11 + z1]);
        }

        // nested lerp: z, then y, then x
        float a00x = wz0 * c000.x + wz1 * c001.x;
        float a00y = wz0 * c000.y + wz1 * c001.y;
        float a01x = wz0 * c010.x + wz1 * c011.x;
        float a01y = wz0 * c010.y + wz1 * c011.y;
        float a10x = wz0 * c100.x + wz1 * c101.x;
        float a10y = wz0 * c100.y + wz1 * c101.y;
        float a11x = wz0 * c110.x + wz1 * c111.x;
        float a11y = wz0 * c110.y + wz1 * c111.y;

        float b0x = wy0 * a00x + wy1 * a01x;
        float b0y = wy0 * a00y + wy1 * a01y;
        float b1x = wy0 * a10x + wy1 * a11x;
        float b1y = wy0 * a10y + wy1 * a11y;

        float2 o;
        o.x = wx0 * b0x + wx1 * b1x;
        o.y = wx0 * b0y + wx1 * b1y;
        out[i] = o;
    }
}

extern "C" void kernel_launch(void* const* d_in, const int* in_sizes, int n_in,
                              void* d_out, int out_size)
{
    const float* vol = (const float*)d_in[0];   // [2,160,192,224,2]; batch 0 at base
    const float* trf = (const float*)d_in[1];   // [2,160,192,224,3]; batch 0 at base
    float2* out = (float2*)d_out;               // [160,192,224,2]

    // idempotent, no allocation; needed for >48KB dynamic smem
    cudaFuncSetAttribute(st_warp_kernel,
                         cudaFuncAttributeMaxDynamicSharedMemorySize, SMEM_BYTES);

    dim3 grid(D0 / TX, D1 / TY, D2 / TZ);   // 20 x 24 x 4
    st_warp_kernel<<<grid, NTHREADS, SMEM_BYTES>>>(vol, trf, out);
}

// round 9
// speedup vs baseline: 1.8969x; 1.8969x over previous
#include <cuda_runtime.h>

// SpatialTransformer: trilinear warp of vol[0] ([160,192,224,2] f32) by dense
// shift field trf[0] ([160,192,224,3] f32). Reference semantics: loc clipped,
// loc0=clip(floor), loc1=clip(loc0+1), w_c0=loc1-loc.
//
// R8 post-mortem: smem tile worked (L1 35%) but ALU=54%/occ=24% killed it.
// This version: block = 8x8x56 output tile, 448 threads (z,y), halo +/-2
// (13x13x61 float2, pitch 63 = 85KB smem -> 2 blocks/SM, 28 warps), zero
// div/mod in hot paths, delta-based corner addressing. ~1.5% of voxels whose
// shift exceeds the halo take a predicated gmem fallback (identical math).

static constexpr int D0 = 160;
static constexpr int D1 = 192;
static constexpr int D2 = 224;

static constexpr int TX = 8, TY = 8, TZ = 56;      // output tile
static constexpr int H  = 2;                       // halo
static constexpr int HX = TX + 2 * H + 1;          // 13
static constexpr int HY = TY + 2 * H + 1;          // 13
static constexpr int HZ = TZ + 2 * H + 1;          // 61
static constexpr int ZP = 63;                      // padded z pitch (float2)
static constexpr int NTHREADS = TZ * TY;           // 448 (14 warps)
static constexpr int SMEM_BYTES = HX * HY * ZP * (int)sizeof(float2);  // 85176

__global__ __launch_bounds__(NTHREADS, 2) void st_warp_kernel(
    const float* __restrict__ vol,   // [D0,D1,D2,2]
    const float* __restrict__ trf,   // [D0,D1,D2,3]
    float2* __restrict__ out)        // [D0,D1,D2] of float2
{
    extern __shared__ float2 sv[];   // [HX*HY][ZP]

    const float2* __restrict__ v2 = (const float2*)vol;

    const int X0 = blockIdx.x * TX;
    const int Y0 = blockIdx.y * TY;
    const int Z0 = blockIdx.z * TZ;

    const int tid  = threadIdx.y * TZ + threadIdx.x;
    const int wid  = tid >> 5;
    const int lane = tid & 31;

    // ---- stage halo'd tile: one warp per row, lanes along z (coalesced) ----
    for (int r = wid; r < HX * HY; r += NTHREADS / 32) {
        int px = r / HY;                 // one div per ~12 rows per warp
        int py = r - px * HY;
        int gx = min(max(X0 - H + px, 0), D0 - 1);
        int gy = min(max(Y0 - H + py, 0), D1 - 1);
        const float2* __restrict__ src = v2 + (gx * D1 + gy) * D2;
        float2* __restrict__ dst = sv + r * ZP;
        for (int pz = lane; pz < HZ; pz += 32) {
            int gz = min(max(Z0 - H + pz, 0), D2 - 1);
            dst[pz] = src[gz];
        }
    }
    __syncthreads();

    const float mx = (float)(D0 - 1);
    const float my = (float)(D1 - 1);
    const float mz = (float)(D2 - 1);

    const int z  = threadIdx.x;          // 0..55
    const int yl = threadIdx.y;          // 0..7
    const int zg = Z0 + z;
    const int y  = Y0 + yl;

    #pragma unroll 2
    for (int xl = 0; xl < TX; xl++) {
        int x = X0 + xl;
        int i = (x * D1 + y) * D2 + zg;  // flat voxel index

        float sx = __ldg(&trf[3 * i + 0]);
        float sy = __ldg(&trf[3 * i + 1]);
        float sz = __ldg(&trf[3 * i + 2]);

        float lx = fminf(fmaxf((float)x  + sx, 0.0f), mx);
        float ly = fminf(fmaxf((float)y  + sy, 0.0f), my);
        float lz = fminf(fmaxf((float)zg + sz, 0.0f), mz);

        float fx0 = floorf(lx), fy0 = floorf(ly), fz0 = floorf(lz);
        float fx1 = fminf(fx0 + 1.0f, mx);
        float fy1 = fminf(fy0 + 1.0f, my);
        float fz1 = fminf(fz0 + 1.0f, mz);

        // reference weights: w_c0 = loc1 - loc, w_c1 = 1 - w_c0
        float wx0 = fx1 - lx, wx1 = 1.0f - wx0;
        float wy0 = fy1 - ly, wy1 = 1.0f - wy0;
        float wz0 = fz1 - lz, wz1 = 1.0f - wz0;

        int x0 = (int)fx0, x1 = (int)fx1;
        int y0 = (int)fy0, y1 = (int)fy1;
        int z0 = (int)fz0, z1 = (int)fz1;

        // tile-local coords and deltas
        int tix = x0 - X0 + H;           // need [0, HX-2] with x1 in tile
        int tiy = y0 - Y0 + H;
        int tiz = z0 - Z0 + H;
        int dX = (x1 - x0) * (HY * ZP);  // 0 or HY*ZP
        int dY = (y1 - y0) * ZP;
        int dz = z1 - z0;

        bool inTile = ((unsigned)tix < (unsigned)(HX - 1) || (tix == HX - 1 && dX == 0)) &
                      ((unsigned)tiy < (unsigned)(HY - 1) || (tiy == HY - 1 && dY == 0)) &
                      ((unsigned)tiz < (unsigned)(HZ - 1) || (tiz == HZ - 1 && dz == 0));

        float2 c000, c001, c010, c011, c100, c101, c110, c111;
        if (inTile) {
            const float2* p = sv + (tix * HY + tiy) * ZP + tiz;
            c000 = p[0];            c001 = p[dz];
            c010 = p[dY];           c011 = p[dY + dz];
            c100 = p[dX];           c101 = p[dX + dz];
            c110 = p[dX + dY];      c111 = p[dX + dY + dz];
        } else {
            int bx0 = x0 * D1, bx1 = x1 * D1;
            int r00 = (bx0 + y0) * D2;
            int r01 = (bx0 + y1) * D2;
            int r10 = (bx1 + y0) * D2;
            int r11 = (bx1 + y1) * D2;
            c000 = __ldg(&v2[r00 + z0]);  c001 = __ldg(&v2[r00 + z1]);
            c010 = __ldg(&v2[r01 + z0]);  c011 = __ldg(&v2[r01 + z1]);
            c100 = __ldg(&v2[r10 + z0]);  c101 = __ldg(&v2[r10 + z1]);
            c110 = __ldg(&v2[r11 + z0]);  c111 = __ldg(&v2[r11 + z1]);
        }

        // nested lerp: z, then y, then x
        float a00x = wz0 * c000.x + wz1 * c001.x;
        float a00y = wz0 * c000.y + wz1 * c001.y;
        float a01x = wz0 * c010.x + wz1 * c011.x;
        float a01y = wz0 * c010.y + wz1 * c011.y;
        float a10x = wz0 * c100.x + wz1 * c101.x;
        float a10y = wz0 * c100.y + wz1 * c101.y;
        float a11x = wz0 * c110.x + wz1 * c111.x;
        float a11y = wz0 * c110.y + wz1 * c111.y;

        float b0x = wy0 * a00x + wy1 * a01x;
        float b0y = wy0 * a00y + wy1 * a01y;
        float b1x = wy0 * a10x + wy1 * a11x;
        float b1y = wy0 * a10y + wy1 * a11y;

        float2 o;
        o.x = wx0 * b0x + wx1 * b1x;
        o.y = wx0 * b0y + wx1 * b1y;
        out[i] = o;
    }
}

extern "C" void kernel_launch(void* const* d_in, const int* in_sizes, int n_in,
                              void* d_out, int out_size)
{
    const float* vol = (const float*)d_in[0];   // [2,160,192,224,2]; batch 0 at base
    const float* trf = (const float*)d_in[1];   // [2,160,192,224,3]; batch 0 at base
    float2* out = (float2*)d_out;               // [160,192,224,2]

    cudaFuncSetAttribute(st_warp_kernel,
                         cudaFuncAttributeMaxDynamicSharedMemorySize, SMEM_BYTES);

    dim3 block(TZ, TY, 1);                  // 56 x 8 = 448 threads
    dim3 grid(D0 / TX, D1 / TY, D2 / TZ);   // 20 x 24 x 4
    st_warp_kernel<<<grid, block, SMEM_BYTES>>>(vol, trf, out);
}

// round 10
// speedup vs baseline: 2.1196x; 1.1174x over previous
#include <cuda_runtime.h>

// SpatialTransformer: trilinear warp of vol[0] ([160,192,224,2] f32) by dense
// shift field trf[0] ([160,192,224,3] f32). Reference semantics: loc clipped,
// loc0=clip(floor), loc1=clip(loc0+1), w_c0=loc1-loc.
//
// R9 post-mortem: tile kernel latency-bound (issue 29%, no pipe >40%).
// This version keeps the 8x8x56 tile + 13x13x61 halo (+/-2, 85KB, 2 blk/SM)
// and attacks latency: trf loads software-pipelined (first pair issued before
// __syncthreads, next pair prefetched during compute), xl fully unrolled as
// 4 pipelined pairs for 16-deep independent LDS per pair.

static constexpr int D0 = 160;
static constexpr int D1 = 192;
static constexpr int D2 = 224;

static constexpr int TX = 8, TY = 8, TZ = 56;      // output tile
static constexpr int H  = 2;                       // halo
static constexpr int HX = TX + 2 * H + 1;          // 13
static constexpr int HY = TY + 2 * H + 1;          // 13
static constexpr int HZ = TZ + 2 * H + 1;          // 61
static constexpr int ZP = 63;                      // padded z pitch (float2)
static constexpr int NTHREADS = TZ * TY;           // 448 (14 warps)
static constexpr int SMEM_BYTES = HX * HY * ZP * (int)sizeof(float2);  // 85176

struct V2 { float x, y; };

// Trilinear sample for one voxel; corners from smem tile when in range,
// rare gmem fallback otherwise. Identical math to reference.
static __device__ __forceinline__ float2 interp_one(
    const float2* __restrict__ sv, const float2* __restrict__ v2,
    int x, int y, int zg, int X0, int Y0, int Z0,
    float sx, float sy, float sz)
{
    const float mx = (float)(D0 - 1);
    const float my = (float)(D1 - 1);
    const float mz = (float)(D2 - 1);

    float lx = fminf(fmaxf((float)x  + sx, 0.0f), mx);
    float ly = fminf(fmaxf((float)y  + sy, 0.0f), my);
    float lz = fminf(fmaxf((float)zg + sz, 0.0f), mz);

    float fx0 = floorf(lx), fy0 = floorf(ly), fz0 = floorf(lz);
    float fx1 = fminf(fx0 + 1.0f, mx);
    float fy1 = fminf(fy0 + 1.0f, my);
    float fz1 = fminf(fz0 + 1.0f, mz);

    float wx0 = fx1 - lx, wx1 = 1.0f - wx0;
    float wy0 = fy1 - ly, wy1 = 1.0f - wy0;
    float wz0 = fz1 - lz, wz1 = 1.0f - wz0;

    int x0 = (int)fx0, x1 = (int)fx1;
    int y0 = (int)fy0, y1 = (int)fy1;
    int z0 = (int)fz0, z1 = (int)fz1;

    int tix = x0 - X0 + H;
    int tiy = y0 - Y0 + H;
    int tiz = z0 - Z0 + H;
    int dX = (x1 - x0) * (HY * ZP);
    int dY = (y1 - y0) * ZP;
    int dz = z1 - z0;

    bool inTile = ((unsigned)tix < (unsigned)(HX - 1) || (tix == HX - 1 && dX == 0)) &
                  ((unsigned)tiy < (unsigned)(HY - 1) || (tiy == HY - 1 && dY == 0)) &
                  ((unsigned)tiz < (unsigned)(HZ - 1) || (tiz == HZ - 1 && dz == 0));

    float2 c000, c001, c010, c011, c100, c101, c110, c111;
    if (inTile) {
        const float2* p = sv + (tix * HY + tiy) * ZP + tiz;
        c000 = p[0];            c001 = p[dz];
        c010 = p[dY];           c011 = p[dY + dz];
        c100 = p[dX];           c101 = p[dX + dz];
        c110 = p[dX + dY];      c111 = p[dX + dY + dz];
    } else {
        int bx0 = x0 * D1, bx1 = x1 * D1;
        int r00 = (bx0 + y0) * D2;
        int r01 = (bx0 + y1) * D2;
        int r10 = (bx1 + y0) * D2;
        int r11 = (bx1 + y1) * D2;
        c000 = __ldg(&v2[r00 + z0]);  c001 = __ldg(&v2[r00 + z1]);
        c010 = __ldg(&v2[r01 + z0]);  c011 = __ldg(&v2[r01 + z1]);
        c100 = __ldg(&v2[r10 + z0]);  c101 = __ldg(&v2[r10 + z1]);
        c110 = __ldg(&v2[r11 + z0]);  c111 = __ldg(&v2[r11 + z1]);
    }

    float a00x = wz0 * c000.x + wz1 * c001.x;
    float a00y = wz0 * c000.y + wz1 * c001.y;
    float a01x = wz0 * c010.x + wz1 * c011.x;
    float a01y = wz0 * c010.y + wz1 * c011.y;
    float a10x = wz0 * c100.x + wz1 * c101.x;
    float a10y = wz0 * c100.y + wz1 * c101.y;
    float a11x = wz0 * c110.x + wz1 * c111.x;
    float a11y = wz0 * c110.y + wz1 * c111.y;

    float b0x = wy0 * a00x + wy1 * a01x;
    float b0y = wy0 * a00y + wy1 * a01y;
    float b1x = wy0 * a10x + wy1 * a11x;
    float b1y = wy0 * a10y + wy1 * a11y;

    float2 o;
    o.x = wx0 * b0x + wx1 * b1x;
    o.y = wx0 * b0y + wx1 * b1y;
    return o;
}

__global__ __launch_bounds__(NTHREADS, 2) void st_warp_kernel(
    const float* __restrict__ vol,   // [D0,D1,D2,2]
    const float* __restrict__ trf,   // [D0,D1,D2,3]
    float2* __restrict__ out)        // [D0,D1,D2] of float2
{
    extern __shared__ float2 sv[];   // [HX*HY][ZP]

    const float2* __restrict__ v2 = (const float2*)vol;

    const int X0 = blockIdx.x * TX;
    const int Y0 = blockIdx.y * TY;
    const int Z0 = blockIdx.z * TZ;

    const int tid  = threadIdx.y * TZ + threadIdx.x;
    const int wid  = tid >> 5;
    const int lane = tid & 31;

    // ---- stage halo'd tile: one warp per row, lanes along z (coalesced) ----
    for (int r = wid; r < HX * HY; r += NTHREADS / 32) {
        int px = r / HY;
        int py = r - px * HY;
        int gx = min(max(X0 - H + px, 0), D0 - 1);
        int gy = min(max(Y0 - H + py, 0), D1 - 1);
        const float2* __restrict__ src = v2 + (gx * D1 + gy) * D2;
        float2* __restrict__ dst = sv + r * ZP;
        for (int pz = lane; pz < HZ; pz += 32) {
            int gz = min(max(Z0 - H + pz, 0), D2 - 1);
            dst[pz] = src[gz];
        }
    }

    const int z  = threadIdx.x;          // 0..55
    const int yl = threadIdx.y;          // 0..7
    const int zg = Z0 + z;
    const int y  = Y0 + yl;
    const int istep = D1 * D2;
    const int ibase = (X0 * D1 + y) * D2 + zg;

    // prefetch trf for pair 0 (xl=0,1) BEFORE the barrier: overlaps the
    // entire tile-stage + __syncthreads with the ~600cyc gmem latency
    float psx[2], psy[2], psz[2];
    {
        const float* t0 = trf + 3 * (size_t)ibase;
        const float* t1 = t0 + 3 * istep;
        psx[0] = __ldg(t0 + 0); psy[0] = __ldg(t0 + 1); psz[0] = __ldg(t0 + 2);
        psx[1] = __ldg(t1 + 0); psy[1] = __ldg(t1 + 1); psz[1] = __ldg(t1 + 2);
    }

    __syncthreads();

    #pragma unroll
    for (int p = 0; p < TX / 2; p++) {
        // prefetch next pair's trf while this pair computes
        float nsx[2], nsy[2], nsz[2];
        if (p < TX / 2 - 1) {
            const float* t0 = trf + 3 * ((size_t)ibase + (2 * p + 2) * (size_t)istep);
            const float* t1 = t0 + 3 * istep;
            nsx[0] = __ldg(t0 + 0); nsy[0] = __ldg(t0 + 1); nsz[0] = __ldg(t0 + 2);
            nsx[1] = __ldg(t1 + 0); nsy[1] = __ldg(t1 + 1); nsz[1] = __ldg(t1 + 2);
        }

        #pragma unroll
        for (int q = 0; q < 2; q++) {
            int xl = 2 * p + q;
            int x = X0 + xl;
            float2 o = interp_one(sv, v2, x, y, zg, X0, Y0, Z0,
                                  psx[q], psy[q], psz[q]);
            out[ibase + xl * istep] = o;
        }

        psx[0] = nsx[0]; psy[0] = nsy[0]; psz[0] = nsz[0];
        psx[1] = nsx[1]; psy[1] = nsy[1]; psz[1] = nsz[1];
    }
}

extern "C" void kernel_launch(void* const* d_in, const int* in_sizes, int n_in,
                              void* d_out, int out_size)
{
    const float* vol = (const float*)d_in[0];   // [2,160,192,224,2]; batch 0 at base
    const float* trf = (const float*)d_in[1];   // [2,160,192,224,3]; batch 0 at base
    float2* out = (float2*)d_out;               // [160,192,224,2]

    cudaFuncSetAttribute(st_warp_kernel,
                         cudaFuncAttributeMaxDynamicSharedMemorySize, SMEM_BYTES);

    dim3 block(TZ, TY, 1);                  // 56 x 8 = 448 threads
    dim3 grid(D0 / TX, D1 / TY, D2 / TZ);   // 20 x 24 x 4
    st_warp_kernel<<<grid, block, SMEM_BYTES>>>(vol, trf, out);
}

// round 12
// speedup vs baseline: 2.1495x; 1.0141x over previous
#include <cuda_runtime.h>

// SpatialTransformer: trilinear warp of vol[0] ([160,192,224,2] f32) by dense
// shift field trf[0] ([160,192,224,3] f32). Reference semantics: loc clipped,
// loc0=clip(floor), loc1=clip(loc0+1), w_c0=loc1-loc.
//
// Tile kernel v4: 8x8x56 tile, 13x13x61 halo (+/-2, 85KB smem, 2 blocks/SM).
// R10 fixes: clamped-coordinate smem path (no dual-path divergence; rare
// corner OVERWRITE from gmem for out-of-halo lanes), 32-bit addressing,
// pair-pipelined trf prefetch retained.

static constexpr int D0 = 160;
static constexpr int D1 = 192;
static constexpr int D2 = 224;

static constexpr int TX = 8, TY = 8, TZ = 56;      // output tile
static constexpr int H  = 2;                       // halo
static constexpr int HX = TX + 2 * H + 1;          // 13
static constexpr int HY = TY + 2 * H + 1;          // 13
static constexpr int HZ = TZ + 2 * H + 1;          // 61
static constexpr int ZP = 63;                      // padded z pitch (float2)
static constexpr int NTHREADS = TZ * TY;           // 448 (14 warps)
static constexpr int SMEM_BYTES = HX * HY * ZP * (int)sizeof(float2);  // 85176

__global__ __launch_bounds__(NTHREADS, 2) void st_warp_kernel(
    const float* __restrict__ vol,   // [D0,D1,D2,2]
    const float* __restrict__ trf,   // [D0,D1,D2,3]
    float2* __restrict__ out)        // [D0,D1,D2] of float2
{
    extern __shared__ float2 sv[];   // [HX*HY][ZP]

    const float2* __restrict__ v2 = (const float2*)vol;

    const int X0 = blockIdx.x * TX;
    const int Y0 = blockIdx.y * TY;
    const int Z0 = blockIdx.z * TZ;

    const int tid  = threadIdx.y * TZ + threadIdx.x;
    const int wid  = tid >> 5;
    const int lane = tid & 31;

    // ---- stage halo'd tile: one warp per row, lanes along z (coalesced) ----
    for (int r = wid; r < HX * HY; r += NTHREADS / 32) {
        int px = r / HY;
        int py = r - px * HY;
        int gx = min(max(X0 - H + px, 0), D0 - 1);
        int gy = min(max(Y0 - H + py, 0), D1 - 1);
        const float2* __restrict__ src = v2 + (gx * D1 + gy) * D2;
        float2* __restrict__ dst = sv + r * ZP;
        for (int pz = lane; pz < HZ; pz += 32) {
            int gz = min(max(Z0 - H + pz, 0), D2 - 1);
            dst[pz] = src[gz];
        }
    }

    const int z  = threadIdx.x;          // 0..55
    const int yl = threadIdx.y;          // 0..7
    const int zg = Z0 + z;
    const int y  = Y0 + yl;
    const int istep = D1 * D2;
    const int ibase = (X0 * D1 + y) * D2 + zg;   // fits in int (max ~6.9M)

    const float mx = (float)(D0 - 1);
    const float my = (float)(D1 - 1);
    const float mz = (float)(D2 - 1);
    const float xb = (float)X0;
    const float yf = (float)y;
    const float zf = (float)zg;
    const int   bx = X0 - H, by = Y0 - H, bz = Z0 - H;  // tile origins

    // prefetch trf for pair 0 BEFORE the barrier (overlaps tile stage)
    float psx[2], psy[2], psz[2];
    {
        const float* t0 = trf + 3 * ibase;
        psx[0] = __ldg(t0);             psy[0] = __ldg(t0 + 1);
        psz[0] = __ldg(t0 + 2);
        const float* t1 = t0 + 3 * istep;
        psx[1] = __ldg(t1);             psy[1] = __ldg(t1 + 1);
        psz[1] = __ldg(t1 + 2);
    }

    __syncthreads();

    #pragma unroll
    for (int p = 0; p < TX / 2; p++) {
        float nsx[2], nsy[2], nsz[2];
        if (p < TX / 2 - 1) {
            const float* t0 = trf + 3 * (ibase + (2 * p + 2) * istep);
            nsx[0] = __ldg(t0);         nsy[0] = __ldg(t0 + 1);
            nsz[0] = __ldg(t0 + 2);
            const float* t1 = t0 + 3 * istep;
            nsx[1] = __ldg(t1);         nsy[1] = __ldg(t1 + 1);
            nsz[1] = __ldg(t1 + 2);
        }

        #pragma unroll
        for (int q = 0; q < 2; q++) {
            int xl = 2 * p + q;
            float xf = xb + (float)xl;

            float lx = fminf(fmaxf(xf + psx[q], 0.0f), mx);
            float ly = fminf(fmaxf(yf + psy[q], 0.0f), my);
            float lz = fminf(fmaxf(zf + psz[q], 0.0f), mz);

            float fx0 = floorf(lx), fy0 = floorf(ly), fz0 = floorf(lz);
            float fx1 = fminf(fx0 + 1.0f, mx);
            float fy1 = fminf(fy0 + 1.0f, my);
            float fz1 = fminf(fz0 + 1.0f, mz);

            float wx0 = fx1 - lx, wx1 = 1.0f - wx0;
            float wy0 = fy1 - ly, wy1 = 1.0f - wy0;
            float wz0 = fz1 - lz, wz1 = 1.0f - wz0;

            int x0 = (int)fx0, x1 = (int)fx1;
            int y0 = (int)fy0, y1 = (int)fy1;
            int z0 = (int)fz0, z1 = (int)fz1;

            // tile coords (may be out of range) and clamped versions
            int tx0 = x0 - bx, tx1 = x1 - bx;
            int ty0 = y0 - by, ty1 = y1 - by;
            int tz0 = z0 - bz, tz1 = z1 - bz;
            int cx0 = min(max(tx0, 0), HX - 1), cx1 = min(max(tx1, 0), HX - 1);
            int cy0 = min(max(ty0, 0), HY - 1), cy1 = min(max(ty1, 0), HY - 1);
            int cz0 = min(max(tz0, 0), HZ - 1), cz1 = min(max(tz1, 0), HZ - 1);
            bool ok = (cx0 == tx0) & (cx1 == tx1) &
                      (cy0 == ty0) & (cy1 == ty1) &
                      (cz0 == tz0) & (cz1 == tz1);

            // always-run smem path (exact whenever ok)
            int a0 = cx0 * HY, a1 = cx1 * HY;
            int s00 = (a0 + cy0) * ZP;
            int s01 = (a0 + cy1) * ZP;
            int s10 = (a1 + cy0) * ZP;
            int s11 = (a1 + cy1) * ZP;
            float2 c000 = sv[s00 + cz0], c001 = sv[s00 + cz1];
            float2 c010 = sv[s01 + cz0], c011 = sv[s01 + cz1];
            float2 c100 = sv[s10 + cz0], c101 = sv[s10 + cz1];
            float2 c110 = sv[s11 + cz0], c111 = sv[s11 + cz1];

            if (!ok) {   // rare (~1% of lanes): overwrite with exact gmem corners
                int bx0 = x0 * D1, bx1 = x1 * D1;
                int r00 = (bx0 + y0) * D2;
                int r01 = (bx0 + y1) * D2;
                int r10 = (bx1 + y0) * D2;
                int r11 = (bx1 + y1) * D2;
                c000 = __ldg(&v2[r00 + z0]);  c001 = __ldg(&v2[r00 + z1]);
                c010 = __ldg(&v2[r01 + z0]);  c011 = __ldg(&v2[r01 + z1]);
                c100 = __ldg(&v2[r10 + z0]);  c101 = __ldg(&v2[r10 + z1]);
                c110 = __ldg(&v2[r11 + z0]);  c111 = __ldg(&v2[r11 + z1]);
            }

            // nested lerp: z, then y, then x
            float a00x = wz0 * c000.x + wz1 * c001.x;
            float a00y = wz0 * c000.y + wz1 * c001.y;
            float a01x = wz0 * c010.x + wz1 * c011.x;
            float a01y = wz0 * c010.y + wz1 * c011.y;
            float a10x = wz0 * c100.x + wz1 * c101.x;
            float a10y = wz0 * c100.y + wz1 * c101.y;
            float a11x = wz0 * c110.x + wz1 * c111.x;
            float a11y = wz0 * c110.y + wz1 * c111.y;

            float b0x = wy0 * a00x + wy1 * a01x;
            float b0y = wy0 * a00y + wy1 * a01y;
            float b1x = wy0 * a10x + wy1 * a11x;
            float b1y = wy0 * a10y + wy1 * a11y;

            float2 o;
            o.x = wx0 * b0x + wx1 * b1x;
            o.y = wx0 * b0y + wx1 * b1y;
            out[ibase + xl * istep] = o;
        }

        psx[0] = nsx[0]; psy[0] = nsy[0]; psz[0] = nsz[0];
        psx[1] = nsx[1]; psy[1] = nsy[1]; psz[1] = nsz[1];
    }
}

extern "C" void kernel_launch(void* const* d_in, const int* in_sizes, int n_in,
                              void* d_out, int out_size)
{
    const float* vol = (const float*)d_in[0];   // [2,160,192,224,2]; batch 0 at base
    const float* trf = (const float*)d_in[1];   // [2,160,192,224,3]; batch 0 at base
    float2* out = (float2*)d_out;               // [160,192,224,2]

    cudaFuncSetAttribute(st_warp_kernel,
                         cudaFuncAttributeMaxDynamicSharedMemorySize, SMEM_BYTES);

    dim3 block(TZ, TY, 1);                  // 56 x 8 = 448 threads
    dim3 grid(D0 / TX, D1 / TY, D2 / TZ);   // 20 x 24 x 4
    st_warp_kernel<<<grid, block, SMEM_BYTES>>>(vol, trf, out);
}

// round 14
// speedup vs baseline: 2.5125x; 1.1689x over previous
#include <cuda_runtime.h>

// SpatialTransformer: trilinear warp of vol[0] ([160,192,224,2] f32) by dense
// shift field trf[0] ([160,192,224,3] f32). Reference semantics: loc clipped,
// loc0=clip(floor), loc1=clip(loc0+1), w_c0=loc1-loc.
//
// Tile kernel v5: R12 post-mortem said latency-hiding-limited (issue 34%,
// occ 39.5%, no pipe >45%). Only change: TX 8->5 so smem drops to 65.5KB ->
// 3 blocks/SM (42 warps, occ ~65%). Same loader, same clamped smem path.

static constexpr int D0 = 160;
static constexpr int D1 = 192;
static constexpr int D2 = 224;

static constexpr int TX = 5, TY = 8, TZ = 56;      // output tile
static constexpr int H  = 2;                       // halo
static constexpr int HX = TX + 2 * H + 1;          // 10
static constexpr int HY = TY + 2 * H + 1;          // 13
static constexpr int HZ = TZ + 2 * H + 1;          // 61
static constexpr int ZP = 63;                      // padded z pitch (float2)
static constexpr int NTHREADS = TZ * TY;           // 448 (14 warps)
static constexpr int SMEM_BYTES = HX * HY * ZP * (int)sizeof(float2);  // 65520

__global__ __launch_bounds__(NTHREADS, 3) void st_warp_kernel(
    const float* __restrict__ vol,   // [D0,D1,D2,2]
    const float* __restrict__ trf,   // [D0,D1,D2,3]
    float2* __restrict__ out)        // [D0,D1,D2] of float2
{
    extern __shared__ float2 sv[];   // [HX*HY][ZP]

    const float2* __restrict__ v2 = (const float2*)vol;

    const int X0 = blockIdx.x * TX;
    const int Y0 = blockIdx.y * TY;
    const int Z0 = blockIdx.z * TZ;

    const int tid  = threadIdx.y * TZ + threadIdx.x;
    const int wid  = tid >> 5;
    const int lane = tid & 31;

    // ---- stage halo'd tile: one warp per row, lanes along z (coalesced) ----
    for (int r = wid; r < HX * HY; r += NTHREADS / 32) {
        int px = r / HY;
        int py = r - px * HY;
        int gx = min(max(X0 - H + px, 0), D0 - 1);
        int gy = min(max(Y0 - H + py, 0), D1 - 1);
        const float2* __restrict__ src = v2 + (gx * D1 + gy) * D2;
        float2* __restrict__ dst = sv + r * ZP;
        for (int pz = lane; pz < HZ; pz += 32) {
            int gz = min(max(Z0 - H + pz, 0), D2 - 1);
            dst[pz] = src[gz];
        }
    }

    const int z  = threadIdx.x;          // 0..55
    const int yl = threadIdx.y;          // 0..7
    const int zg = Z0 + z;
    const int y  = Y0 + yl;
    const int istep = D1 * D2;
    const int ibase = (X0 * D1 + y) * D2 + zg;

    const float mx = (float)(D0 - 1);
    const float my = (float)(D1 - 1);
    const float mz = (float)(D2 - 1);
    const float xb = (float)X0;
    const float yf = (float)y;
    const float zf = (float)zg;
    const int   bx = X0 - H, by = Y0 - H, bz = Z0 - H;  // tile origins

    // prefetch trf for xl=0 BEFORE the barrier (overlaps tile stage)
    float psx, psy, psz;
    {
        const float* t0 = trf + 3 * ibase;
        psx = __ldg(t0); psy = __ldg(t0 + 1); psz = __ldg(t0 + 2);
    }

    __syncthreads();

    #pragma unroll
    for (int xl = 0; xl < TX; xl++) {
        // prefetch next voxel's trf while this one computes
        float nsx, nsy, nsz;
        if (xl < TX - 1) {
            const float* t0 = trf + 3 * (ibase + (xl + 1) * istep);
            nsx = __ldg(t0); nsy = __ldg(t0 + 1); nsz = __ldg(t0 + 2);
        }

        float xf = xb + (float)xl;

        float lx = fminf(fmaxf(xf + psx, 0.0f), mx);
        float ly = fminf(fmaxf(yf + psy, 0.0f), my);
        float lz = fminf(fmaxf(zf + psz, 0.0f), mz);

        float fx0 = floorf(lx), fy0 = floorf(ly), fz0 = floorf(lz);
        float fx1 = fminf(fx0 + 1.0f, mx);
        float fy1 = fminf(fy0 + 1.0f, my);
        float fz1 = fminf(fz0 + 1.0f, mz);

        float wx0 = fx1 - lx, wx1 = 1.0f - wx0;
        float wy0 = fy1 - ly, wy1 = 1.0f - wy0;
        float wz0 = fz1 - lz, wz1 = 1.0f - wz0;

        int x0 = (int)fx0, x1 = (int)fx1;
        int y0 = (int)fy0, y1 = (int)fy1;
        int z0 = (int)fz0, z1 = (int)fz1;

        // tile coords (may be out of range) and clamped versions
        int tx0 = x0 - bx, tx1 = x1 - bx;
        int ty0 = y0 - by, ty1 = y1 - by;
        int tz0 = z0 - bz, tz1 = z1 - bz;
        int cx0 = min(max(tx0, 0), HX - 1), cx1 = min(max(tx1, 0), HX - 1);
        int cy0 = min(max(ty0, 0), HY - 1), cy1 = min(max(ty1, 0), HY - 1);
        int cz0 = min(max(tz0, 0), HZ - 1), cz1 = min(max(tz1, 0), HZ - 1);
        bool ok = (cx0 == tx0) & (cx1 == tx1) &
                  (cy0 == ty0) & (cy1 == ty1) &
                  (cz0 == tz0) & (cz1 == tz1);

        // always-run smem path (exact whenever ok)
        int a0 = cx0 * HY, a1 = cx1 * HY;
        int s00 = (a0 + cy0) * ZP;
        int s01 = (a0 + cy1) * ZP;
        int s10 = (a1 + cy0) * ZP;
        int s11 = (a1 + cy1) * ZP;
        float2 c000 = sv[s00 + cz0], c001 = sv[s00 + cz1];
        float2 c010 = sv[s01 + cz0], c011 = sv[s01 + cz1];
        float2 c100 = sv[s10 + cz0], c101 = sv[s10 + cz1];
        float2 c110 = sv[s11 + cz0], c111 = sv[s11 + cz1];

        if (!ok) {   // rare (~1% of lanes): overwrite with exact gmem corners
            int gx0 = x0 * D1, gx1 = x1 * D1;
            int r00 = (gx0 + y0) * D2;
            int r01 = (gx0 + y1) * D2;
            int r10 = (gx1 + y0) * D2;
            int r11 = (gx1 + y1) * D2;
            c000 = __ldg(&v2[r00 + z0]);  c001 = __ldg(&v2[r00 + z1]);
            c010 = __ldg(&v2[r01 + z0]);  c011 = __ldg(&v2[r01 + z1]);
            c100 = __ldg(&v2[r10 + z0]);  c101 = __ldg(&v2[r10 + z1]);
            c110 = __ldg(&v2[r11 + z0]);  c111 = __ldg(&v2[r11 + z1]);
        }

        // nested lerp: z, then y, then x
        float a00x = wz0 * c000.x + wz1 * c001.x;
        float a00y = wz0 * c000.y + wz1 * c001.y;
        float a01x = wz0 * c010.x + wz1 * c011.x;
        float a01y = wz0 * c010.y + wz1 * c011.y;
        float a10x = wz0 * c100.x + wz1 * c101.x;
        float a10y = wz0 * c100.y + wz1 * c101.y;
        float a11x = wz0 * c110.x + wz1 * c111.x;
        float a11y = wz0 * c110.y + wz1 * c111.y;

        float b0x = wy0 * a00x + wy1 * a01x;
        float b0y = wy0 * a00y + wy1 * a01y;
        float b1x = wy0 * a10x + wy1 * a11x;
        float b1y = wy0 * a10y + wy1 * a11y;

        float2 o;
        o.x = wx0 * b0x + wx1 * b1x;
        o.y = wx0 * b0y + wx1 * b1y;
        out[ibase + xl * istep] = o;

        psx = nsx; psy = nsy; psz = nsz;
    }
}

extern "C" void kernel_launch(void* const* d_in, const int* in_sizes, int n_in,
                              void* d_out, int out_size)
{
    const float* vol = (const float*)d_in[0];   // [2,160,192,224,2]; batch 0 at base
    const float* trf = (const float*)d_in[1];   // [2,160,192,224,3]; batch 0 at base
    float2* out = (float2*)d_out;               // [160,192,224,2]

    cudaFuncSetAttribute(st_warp_kernel,
                         cudaFuncAttributeMaxDynamicSharedMemorySize, SMEM_BYTES);

    dim3 block(TZ, TY, 1);                  // 56 x 8 = 448 threads
    dim3 grid(D0 / TX, D1 / TY, D2 / TZ);   // 32 x 24 x 4
    st_warp_kernel<<<grid, block, SMEM_BYTES>>>(vol, trf, out);
}